// round 1
// baseline (speedup 1.0000x reference)
#include <cuda_runtime.h>
#include <cuda_bf16.h>
#include <cstdint>

// Problem constants (fixed by the reference: B=4096, D=512)
#define BHALF 4096
#define NROWS 8192
#define DIM   512

constexpr int TILE = 128;       // output tile 128x128
constexpr int KCH  = 64;        // K chunk
constexpr int LDST = 72;        // padded smem stride (bf16 elems): 144B rows, conflict-friendly
constexpr int SMEM_BYTES = 2 * TILE * LDST * 2;   // 36864 B (< 48KB default)

// Scratch (no cudaMalloc allowed)
__device__ __nv_bfloat16 g_zn[(size_t)NROWS * DIM];   // normalized rows, bf16
__device__ float g_rowsum[NROWS];                     // sum_j exp(2*dot) excl. diagonal

// ---------------------------------------------------------------------------
// helpers
// ---------------------------------------------------------------------------
__device__ __forceinline__ uint32_t smem_u32(const void* p) {
    return (uint32_t)__cvta_generic_to_shared(p);
}

__device__ __forceinline__ void ldmat_x4(uint32_t& r0, uint32_t& r1, uint32_t& r2, uint32_t& r3,
                                         uint32_t addr) {
    asm volatile("ldmatrix.sync.aligned.m8n8.x4.shared.b16 {%0,%1,%2,%3}, [%4];\n"
                 : "=r"(r0), "=r"(r1), "=r"(r2), "=r"(r3)
                 : "r"(addr));
}

__device__ __forceinline__ void mma16816(float* c,
                                         const uint32_t* a,      // 4 regs
                                         uint32_t b0, uint32_t b1) {
    asm volatile(
        "mma.sync.aligned.m16n8k16.row.col.f32.bf16.bf16.f32 "
        "{%0,%1,%2,%3}, {%4,%5,%6,%7}, {%8,%9}, {%0,%1,%2,%3};\n"
        : "+f"(c[0]), "+f"(c[1]), "+f"(c[2]), "+f"(c[3])
        : "r"(a[0]), "r"(a[1]), "r"(a[2]), "r"(a[3]), "r"(b0), "r"(b1));
}

// ---------------------------------------------------------------------------
// Kernel 1: L2-normalize each of the 8192 rows (fp32 in -> bf16 out),
// zero the row-sum accumulators and the output scalar.
// grid = NROWS blocks, 128 threads
// ---------------------------------------------------------------------------
__global__ void __launch_bounds__(128) normalize_kernel(const float* __restrict__ zi,
                                                        const float* __restrict__ zj,
                                                        float* __restrict__ d_out) {
    const int r = blockIdx.x;
    const int t = threadIdx.x;
    const float* src = (r < BHALF) ? (zi + (size_t)r * DIM)
                                   : (zj + (size_t)(r - BHALF) * DIM);
    float4 v = ((const float4*)src)[t];
    float ss = v.x * v.x + v.y * v.y + v.z * v.z + v.w * v.w;
    #pragma unroll
    for (int o = 16; o; o >>= 1) ss += __shfl_xor_sync(0xffffffffu, ss, o);
    __shared__ float ws[4];
    if ((t & 31) == 0) ws[t >> 5] = ss;
    __syncthreads();
    float rn = rsqrtf(ws[0] + ws[1] + ws[2] + ws[3]);

    __nv_bfloat162* dst = (__nv_bfloat162*)(g_zn + (size_t)r * DIM) + t * 2;
    dst[0] = __float22bfloat162_rn(make_float2(v.x * rn, v.y * rn));
    dst[1] = __float22bfloat162_rn(make_float2(v.z * rn, v.w * rn));

    if (t == 0) {
        g_rowsum[r] = 0.0f;
        if (r == 0) d_out[0] = 0.0f;
    }
}

// ---------------------------------------------------------------------------
// Kernel 2: tiled bf16 GEMM (sim = Z Z^T) with fused exp + diagonal-skip +
// per-row sum. Each block: 128 rows x 128 cols, full K=512.
// grid = (64, 64), 256 threads (8 warps: 4 along M, 2 along N; warp tile 32x64)
// ---------------------------------------------------------------------------
__global__ void __launch_bounds__(256, 2) gemm_rowsum_kernel() {
    extern __shared__ __nv_bfloat16 sm[];
    __nv_bfloat16* As = sm;
    __nv_bfloat16* Bs = sm + TILE * LDST;

    const int rt = blockIdx.y, ct = blockIdx.x;
    const int rowA0 = rt * TILE, rowB0 = ct * TILE;
    const int tid  = threadIdx.x;
    const int warp = tid >> 5, lane = tid & 31;
    const int wm = warp & 3;       // warp row (0..3) -> 32 rows each
    const int wn = warp >> 2;      // warp col (0..1) -> 64 cols each

    float acc[2][8][4];
    #pragma unroll
    for (int i = 0; i < 2; i++)
        #pragma unroll
        for (int j = 0; j < 8; j++)
            #pragma unroll
            for (int k = 0; k < 4; k++) acc[i][j][k] = 0.0f;

    for (int k0 = 0; k0 < DIM; k0 += KCH) {
        // cooperative loads: 128x64 bf16 per tile, uint4 (8 bf16) per thread x4
        #pragma unroll
        for (int i = 0; i < 4; i++) {
            int lin = tid + i * 256;          // 0..1023
            int r  = lin >> 3;
            int c8 = (lin & 7) << 3;
            *(uint4*)(As + r * LDST + c8) =
                *(const uint4*)(g_zn + (size_t)(rowA0 + r) * DIM + k0 + c8);
            *(uint4*)(Bs + r * LDST + c8) =
                *(const uint4*)(g_zn + (size_t)(rowB0 + r) * DIM + k0 + c8);
        }
        __syncthreads();

        #pragma unroll
        for (int kk = 0; kk < 4; kk++) {
            // A fragments: 2 x m16k16
            uint32_t a[2][4];
            #pragma unroll
            for (int mf = 0; mf < 2; mf++) {
                int row = wm * 32 + mf * 16 + (lane & 15);
                int kc  = kk * 16 + (lane >> 4) * 8;
                ldmat_x4(a[mf][0], a[mf][1], a[mf][2], a[mf][3],
                         smem_u32(As + row * LDST + kc));
            }
            // B fragments: 4 x n16k16 (each x4 = two n8 frags)
            uint32_t b[4][4];
            #pragma unroll
            for (int nn = 0; nn < 4; nn++) {
                int grp = lane >> 3;
                int nr  = wn * 64 + nn * 16 + (lane & 7) + ((grp >> 1) << 3);
                int kc  = kk * 16 + ((grp & 1) << 3);
                ldmat_x4(b[nn][0], b[nn][1], b[nn][2], b[nn][3],
                         smem_u32(Bs + nr * LDST + kc));
            }
            #pragma unroll
            for (int mf = 0; mf < 2; mf++)
                #pragma unroll
                for (int nn = 0; nn < 4; nn++) {
                    mma16816(acc[mf][nn * 2 + 0], a[mf], b[nn][0], b[nn][1]);
                    mma16816(acc[mf][nn * 2 + 1], a[mf], b[nn][2], b[nn][3]);
                }
        }
        __syncthreads();
    }

    // Epilogue: exp(2*dot), skip diagonal, reduce along columns, accumulate.
    float sA[2] = {0.f, 0.f}, sB[2] = {0.f, 0.f};
    #pragma unroll
    for (int mf = 0; mf < 2; mf++) {
        int rowa = rowA0 + wm * 32 + mf * 16 + (lane >> 2);
        int rowb = rowa + 8;
        #pragma unroll
        for (int nf = 0; nf < 8; nf++) {
            int col0 = rowB0 + wn * 64 + nf * 8 + ((lane & 3) << 1);
            float e0 = (rowa == col0)     ? 0.f : __expf(2.0f * acc[mf][nf][0]);
            float e1 = (rowa == col0 + 1) ? 0.f : __expf(2.0f * acc[mf][nf][1]);
            float e2 = (rowb == col0)     ? 0.f : __expf(2.0f * acc[mf][nf][2]);
            float e3 = (rowb == col0 + 1) ? 0.f : __expf(2.0f * acc[mf][nf][3]);
            sA[mf] += e0 + e1;
            sB[mf] += e2 + e3;
        }
    }
    #pragma unroll
    for (int o = 1; o < 4; o <<= 1) {
        sA[0] += __shfl_xor_sync(0xffffffffu, sA[0], o);
        sA[1] += __shfl_xor_sync(0xffffffffu, sA[1], o);
        sB[0] += __shfl_xor_sync(0xffffffffu, sB[0], o);
        sB[1] += __shfl_xor_sync(0xffffffffu, sB[1], o);
    }
    if ((lane & 3) == 0) {
        int r0 = rowA0 + wm * 32 + (lane >> 2);
        atomicAdd(&g_rowsum[r0],      sA[0]);
        atomicAdd(&g_rowsum[r0 + 8],  sB[0]);
        atomicAdd(&g_rowsum[r0 + 16], sA[1]);
        atomicAdd(&g_rowsum[r0 + 24], sB[1]);
    }
}

// ---------------------------------------------------------------------------
// Kernel 3: positive-pair dot per pair + final loss reduction.
// loss = -(1/2B) * sum_r [ 2*dot_pos(r) - log(rowsum_r) ]
// grid = BHALF blocks, 128 threads
// ---------------------------------------------------------------------------
__global__ void __launch_bounds__(128) loss_kernel(float* __restrict__ d_out) {
    const int p = blockIdx.x;
    const int t = threadIdx.x;
    const __nv_bfloat16* a = g_zn + (size_t)p * DIM;
    const __nv_bfloat16* b = g_zn + (size_t)(p + BHALF) * DIM;

    uint2 va = ((const uint2*)a)[t];
    uint2 vb = ((const uint2*)b)[t];
    float2 a0 = __bfloat1622float2(*reinterpret_cast<__nv_bfloat162*>(&va.x));
    float2 a1 = __bfloat1622float2(*reinterpret_cast<__nv_bfloat162*>(&va.y));
    float2 b0 = __bfloat1622float2(*reinterpret_cast<__nv_bfloat162*>(&vb.x));
    float2 b1 = __bfloat1622float2(*reinterpret_cast<__nv_bfloat162*>(&vb.y));
    float d = a0.x * b0.x + a0.y * b0.y + a1.x * b1.x + a1.y * b1.y;

    #pragma unroll
    for (int o = 16; o; o >>= 1) d += __shfl_xor_sync(0xffffffffu, d, o);
    __shared__ float ws[4];
    if ((t & 31) == 0) ws[t >> 5] = d;
    __syncthreads();

    if (t == 0) {
        float dp = ws[0] + ws[1] + ws[2] + ws[3];   // dot(z_p, z_{p+B})
        float den0 = g_rowsum[p];
        float den1 = g_rowsum[p + BHALF];
        // two rows (p and p+B) share the same positive dot
        float contrib = ((2.0f * dp - logf(den0)) + (2.0f * dp - logf(den1)))
                        * (-1.0f / (float)NROWS);
        atomicAdd(d_out, contrib);
    }
}

// ---------------------------------------------------------------------------
extern "C" void kernel_launch(void* const* d_in, const int* in_sizes, int n_in,
                              void* d_out, int out_size) {
    const float* zi = (const float*)d_in[0];
    const float* zj = (const float*)d_in[1];
    float* out = (float*)d_out;

    normalize_kernel<<<NROWS, 128>>>(zi, zj, out);
    gemm_rowsum_kernel<<<dim3(NROWS / TILE, NROWS / TILE), 256, SMEM_BYTES>>>();
    loss_kernel<<<BHALF, 128>>>(out);
}

// round 4
// speedup vs baseline: 1.8551x; 1.8551x over previous
#include <cuda_runtime.h>
#include <cuda_bf16.h>
#include <cstdint>

// Problem constants (fixed by the reference: B=4096, D=512)
#define BHALF 4096
#define NROWS 8192
#define DIM   512

constexpr int TILE  = 128;                       // output tile 128x128
constexpr int KCH   = 64;                        // K chunk
constexpr int NKCH  = DIM / KCH;                 // 8
constexpr int LDST  = 72;                        // padded smem stride (bf16): 144B rows
constexpr int NTILE = NROWS / TILE;              // 64
constexpr int NBLK  = NTILE * (NTILE + 1) / 2;   // 2080 upper-tri tiles
constexpr int MAT_BYTES   = TILE * LDST * 2;     // 18432 per matrix
constexpr int STAGE_BYTES = 2 * MAT_BYTES;       // A+B = 36864
constexpr int SMEM_BYTES  = 2 * STAGE_BYTES;     // 73728 (two stages)

// Scratch (no cudaMalloc allowed)
__device__ __nv_bfloat16 g_zn[(size_t)NROWS * DIM];   // normalized rows, bf16
__device__ float g_rowsum[NROWS];                     // sum_{j!=i} exp(2*dot)
__device__ float g_posdot[BHALF];                     // normalized positive-pair dot

// ---------------------------------------------------------------------------
// helpers
// ---------------------------------------------------------------------------
__device__ __forceinline__ uint32_t smem_u32(const void* p) {
    return (uint32_t)__cvta_generic_to_shared(p);
}
__device__ __forceinline__ void cpasync16(uint32_t s, const void* g) {
    asm volatile("cp.async.cg.shared.global [%0], [%1], 16;\n" :: "r"(s), "l"(g));
}
__device__ __forceinline__ void ldmat_x4(uint32_t& r0, uint32_t& r1, uint32_t& r2, uint32_t& r3,
                                         uint32_t addr) {
    asm volatile("ldmatrix.sync.aligned.m8n8.x4.shared.b16 {%0,%1,%2,%3}, [%4];\n"
                 : "=r"(r0), "=r"(r1), "=r"(r2), "=r"(r3)
                 : "r"(addr));
}
__device__ __forceinline__ void mma16816(float* c, const uint32_t* a,
                                         uint32_t b0, uint32_t b1) {
    asm volatile(
        "mma.sync.aligned.m16n8k16.row.col.f32.bf16.bf16.f32 "
        "{%0,%1,%2,%3}, {%4,%5,%6,%7}, {%8,%9}, {%0,%1,%2,%3};\n"
        : "+f"(c[0]), "+f"(c[1]), "+f"(c[2]), "+f"(c[3])
        : "r"(a[0]), "r"(a[1]), "r"(a[2]), "r"(a[3]), "r"(b0), "r"(b1));
}

// ---------------------------------------------------------------------------
// Kernel 1: per-pair normalize (rows p and p+B), fused positive-pair dot.
// Also zeros rowsums and the output scalar. grid = BHALF, 128 threads.
// ---------------------------------------------------------------------------
__global__ void __launch_bounds__(128) normalize_kernel(const float* __restrict__ zi,
                                                        const float* __restrict__ zj,
                                                        float* __restrict__ d_out) {
    const int p = blockIdx.x;
    const int t = threadIdx.x;
    float4 vi = ((const float4*)(zi + (size_t)p * DIM))[t];
    float4 vj = ((const float4*)(zj + (size_t)p * DIM))[t];
    float ssi = vi.x * vi.x + vi.y * vi.y + vi.z * vi.z + vi.w * vi.w;
    float ssj = vj.x * vj.x + vj.y * vj.y + vj.z * vj.z + vj.w * vj.w;
    float sij = vi.x * vj.x + vi.y * vj.y + vi.z * vj.z + vi.w * vj.w;
    #pragma unroll
    for (int o = 16; o; o >>= 1) {
        ssi += __shfl_xor_sync(0xffffffffu, ssi, o);
        ssj += __shfl_xor_sync(0xffffffffu, ssj, o);
        sij += __shfl_xor_sync(0xffffffffu, sij, o);
    }
    __shared__ float s0[4], s1[4], s2[4];
    if ((t & 31) == 0) { s0[t >> 5] = ssi; s1[t >> 5] = ssj; s2[t >> 5] = sij; }
    __syncthreads();
    float rni = rsqrtf(s0[0] + s0[1] + s0[2] + s0[3]);
    float rnj = rsqrtf(s1[0] + s1[1] + s1[2] + s1[3]);

    __nv_bfloat162* di = (__nv_bfloat162*)(g_zn + (size_t)p * DIM) + t * 2;
    di[0] = __float22bfloat162_rn(make_float2(vi.x * rni, vi.y * rni));
    di[1] = __float22bfloat162_rn(make_float2(vi.z * rni, vi.w * rni));
    __nv_bfloat162* dj = (__nv_bfloat162*)(g_zn + (size_t)(p + BHALF) * DIM) + t * 2;
    dj[0] = __float22bfloat162_rn(make_float2(vj.x * rnj, vj.y * rnj));
    dj[1] = __float22bfloat162_rn(make_float2(vj.z * rnj, vj.w * rnj));

    if (t == 0) {
        g_posdot[p] = (s2[0] + s2[1] + s2[2] + s2[3]) * rni * rnj;
        g_rowsum[p] = 0.0f;
        g_rowsum[p + BHALF] = 0.0f;
        if (p == 0) d_out[0] = 0.0f;
    }
}

// ---------------------------------------------------------------------------
// Kernel 2: symmetric bf16 mma.sync GEMM + fused exp + row/col sums.
// grid = 2080 upper-triangular 128x128 tiles, 256 threads (8 warps: 4M x 2N).
// cp.async 2-stage pipelined K loop. Keep elements with global col > row;
// each kept exp adds to rowsum[row] and rowsum[col].
// ---------------------------------------------------------------------------
__global__ void __launch_bounds__(256, 2) gemm_rowsum_kernel() {
    extern __shared__ __nv_bfloat16 sm[];

    // decode upper-tri tile index
    int id = blockIdx.x, rt = 0, rem = NTILE;
    while (id >= rem) { id -= rem; rem--; rt++; }
    const int ct = rt + id;
    const int rowA0 = rt * TILE, rowB0 = ct * TILE;
    const bool isDiag = (rt == ct);

    const int tid  = threadIdx.x;
    const int warp = tid >> 5, lane = tid & 31;
    const int wm = warp & 3;       // warp row (0..3): 32 rows
    const int wn = warp >> 2;      // warp col (0..1): 64 cols

    const uint32_t sb = smem_u32(sm);

    float acc[2][8][4];
    #pragma unroll
    for (int i = 0; i < 2; i++)
        #pragma unroll
        for (int j = 0; j < 8; j++)
            #pragma unroll
            for (int k = 0; k < 4; k++) acc[i][j][k] = 0.0f;

    // ---- async chunk loader: A (and B unless diag) 128x64 bf16 into stage st
    auto issue_load = [&](int k0, int st) {
        uint32_t sA = sb + st * STAGE_BYTES;
        uint32_t sB = sA + MAT_BYTES;
        const __nv_bfloat16* gA = g_zn + (size_t)rowA0 * DIM + k0;
        const __nv_bfloat16* gB = g_zn + (size_t)rowB0 * DIM + k0;
        #pragma unroll
        for (int i = 0; i < 4; i++) {
            int lin = tid + i * 256;          // 0..1023
            int r  = lin >> 3;
            int c8 = (lin & 7) << 3;
            uint32_t soff = r * (LDST * 2) + c8 * 2;   // bytes; 144*r is 16B-aligned
            cpasync16(sA + soff, gA + (size_t)r * DIM + c8);
            if (!isDiag) cpasync16(sB + soff, gB + (size_t)r * DIM + c8);
        }
        asm volatile("cp.async.commit_group;\n" ::: "memory");
    };

    auto compute = [&](int st) {
        const __nv_bfloat16* As = sm + st * (STAGE_BYTES / 2);
        const __nv_bfloat16* Bs = isDiag ? As : (As + TILE * LDST);
        #pragma unroll
        for (int kk = 0; kk < 4; kk++) {
            uint32_t a[2][4];
            #pragma unroll
            for (int mf = 0; mf < 2; mf++) {
                int row = wm * 32 + mf * 16 + (lane & 15);
                int kc  = kk * 16 + (lane >> 4) * 8;
                ldmat_x4(a[mf][0], a[mf][1], a[mf][2], a[mf][3],
                         smem_u32(As + row * LDST + kc));
            }
            uint32_t b[4][4];
            #pragma unroll
            for (int nn = 0; nn < 4; nn++) {
                int grp = lane >> 3;
                int nr  = wn * 64 + nn * 16 + (lane & 7) + ((grp >> 1) << 3);
                int kc  = kk * 16 + ((grp & 1) << 3);
                ldmat_x4(b[nn][0], b[nn][1], b[nn][2], b[nn][3],
                         smem_u32(Bs + nr * LDST + kc));
            }
            #pragma unroll
            for (int mf = 0; mf < 2; mf++)
                #pragma unroll
                for (int nn = 0; nn < 4; nn++) {
                    mma16816(acc[mf][nn * 2 + 0], a[mf], b[nn][0], b[nn][1]);
                    mma16816(acc[mf][nn * 2 + 1], a[mf], b[nn][2], b[nn][3]);
                }
        }
    };

    issue_load(0, 0);
    #pragma unroll 1
    for (int k = 0; k < NKCH; k++) {
        if (k + 1 < NKCH) {
            issue_load((k + 1) * KCH, (k + 1) & 1);
            asm volatile("cp.async.wait_group 1;\n" ::: "memory");
        } else {
            asm volatile("cp.async.wait_group 0;\n" ::: "memory");
        }
        __syncthreads();
        compute(k & 1);
        __syncthreads();   // all warps done reading before next load overwrites
    }

    // ---- epilogue: exp(2*dot); keep col>row (full off-diag tiles, strict upper
    //      on diag tiles); accumulate row sums and column sums.
    float rs[2][2] = {{0.f, 0.f}, {0.f, 0.f}};   // [mf][ra/rb]
    float cs[8][2];
    #pragma unroll
    for (int nf = 0; nf < 8; nf++) { cs[nf][0] = 0.f; cs[nf][1] = 0.f; }

    #pragma unroll
    for (int mf = 0; mf < 2; mf++) {
        int ra = rowA0 + wm * 32 + mf * 16 + (lane >> 2);
        int rb = ra + 8;
        #pragma unroll
        for (int nf = 0; nf < 8; nf++) {
            int c0 = rowB0 + wn * 64 + nf * 8 + ((lane & 3) << 1);
            float e0 = __expf(2.0f * acc[mf][nf][0]);
            float e1 = __expf(2.0f * acc[mf][nf][1]);
            float e2 = __expf(2.0f * acc[mf][nf][2]);
            float e3 = __expf(2.0f * acc[mf][nf][3]);
            if (isDiag) {
                if (c0     <= ra) e0 = 0.f;
                if (c0 + 1 <= ra) e1 = 0.f;
                if (c0     <= rb) e2 = 0.f;
                if (c0 + 1 <= rb) e3 = 0.f;
            }
            rs[mf][0] += e0 + e1;
            rs[mf][1] += e2 + e3;
            cs[nf][0] += e0 + e2;
            cs[nf][1] += e1 + e3;
        }
    }

    // row sums: reduce across lane&3 (4 threads share a row)
    #pragma unroll
    for (int o = 1; o < 4; o <<= 1) {
        rs[0][0] += __shfl_xor_sync(0xffffffffu, rs[0][0], o);
        rs[0][1] += __shfl_xor_sync(0xffffffffu, rs[0][1], o);
        rs[1][0] += __shfl_xor_sync(0xffffffffu, rs[1][0], o);
        rs[1][1] += __shfl_xor_sync(0xffffffffu, rs[1][1], o);
    }
    if ((lane & 3) == 0) {
        int r0 = rowA0 + wm * 32 + (lane >> 2);
        atomicAdd(&g_rowsum[r0],      rs[0][0]);
        atomicAdd(&g_rowsum[r0 + 8],  rs[0][1]);
        atomicAdd(&g_rowsum[r0 + 16], rs[1][0]);
        atomicAdd(&g_rowsum[r0 + 24], rs[1][1]);
    }

    // col sums: reduce across lane>>2 (8 threads share a column group)
    #pragma unroll
    for (int nf = 0; nf < 8; nf++) {
        #pragma unroll
        for (int o = 4; o < 32; o <<= 1) {
            cs[nf][0] += __shfl_xor_sync(0xffffffffu, cs[nf][0], o);
            cs[nf][1] += __shfl_xor_sync(0xffffffffu, cs[nf][1], o);
        }
    }
    if (lane < 4) {
        #pragma unroll
        for (int nf = 0; nf < 8; nf++) {
            int c0 = rowB0 + wn * 64 + nf * 8 + lane * 2;
            atomicAdd(&g_rowsum[c0],     cs[nf][0]);
            atomicAdd(&g_rowsum[c0 + 1], cs[nf][1]);
        }
    }
}

// ---------------------------------------------------------------------------
// Kernel 3: final loss.
// loss = -(1/2B) * sum_p [4*posdot(p) - log(rs_p) - log(rs_{p+B})]
// ---------------------------------------------------------------------------
__global__ void __launch_bounds__(128) loss_kernel(float* __restrict__ d_out) {
    const int p = blockIdx.x * 128 + threadIdx.x;
    float c = 4.0f * g_posdot[p] - logf(g_rowsum[p]) - logf(g_rowsum[p + BHALF]);
    #pragma unroll
    for (int o = 16; o; o >>= 1) c += __shfl_xor_sync(0xffffffffu, c, o);
    __shared__ float ws[4];
    int t = threadIdx.x;
    if ((t & 31) == 0) ws[t >> 5] = c;
    __syncthreads();
    if (t == 0)
        atomicAdd(d_out, (ws[0] + ws[1] + ws[2] + ws[3]) * (-1.0f / (float)NROWS));
}

// ---------------------------------------------------------------------------
extern "C" void kernel_launch(void* const* d_in, const int* in_sizes, int n_in,
                              void* d_out, int out_size) {
    const float* zi = (const float*)d_in[0];
    const float* zj = (const float*)d_in[1];
    float* out = (float*)d_out;

    static bool attr_set = false;
    if (!attr_set) {
        cudaFuncSetAttribute(gemm_rowsum_kernel,
                             cudaFuncAttributeMaxDynamicSharedMemorySize, SMEM_BYTES);
        attr_set = true;
    }

    normalize_kernel<<<BHALF, 128>>>(zi, zj, out);
    gemm_rowsum_kernel<<<NBLK, 256, SMEM_BYTES>>>();
    loss_kernel<<<32, 128>>>(out);
}

// round 5
// speedup vs baseline: 1.9356x; 1.0434x over previous
#include <cuda_runtime.h>
#include <cuda_bf16.h>
#include <cstdint>

// Problem constants (fixed by the reference: B=4096, D=512)
#define BHALF 4096
#define NROWS 8192
#define DIM   512

constexpr int TILE  = 128;                       // output tile 128x128
constexpr int KCH   = 64;                        // K chunk
constexpr int NKCH  = DIM / KCH;                 // 8
constexpr int LDST  = 72;                        // padded smem stride (bf16): 144B rows
constexpr int NTILE = NROWS / TILE;              // 64
constexpr int NBLK  = NTILE * (NTILE + 1) / 2;   // 2080 upper-tri tiles
constexpr int MAT_BYTES   = TILE * LDST * 2;     // 18432 per matrix
constexpr int STAGE_BYTES = 2 * MAT_BYTES;       // A+B = 36864
constexpr int SMEM_BYTES  = 2 * STAGE_BYTES;     // 73728 (two stages)

// Scratch (no cudaMalloc allowed)
__device__ __nv_bfloat16 g_zn[(size_t)NROWS * DIM];   // normalized rows, bf16
__device__ float g_rowsum[NROWS];                     // sum_{j!=i} exp(2*dot)
__device__ float g_posdot[BHALF];                     // normalized positive-pair dot

// ---------------------------------------------------------------------------
// helpers
// ---------------------------------------------------------------------------
__device__ __forceinline__ uint32_t smem_u32(const void* p) {
    return (uint32_t)__cvta_generic_to_shared(p);
}
__device__ __forceinline__ void cpasync16(uint32_t s, const void* g) {
    asm volatile("cp.async.cg.shared.global [%0], [%1], 16;\n" :: "r"(s), "l"(g));
}
__device__ __forceinline__ void ldmat_x4(uint32_t& r0, uint32_t& r1, uint32_t& r2, uint32_t& r3,
                                         uint32_t addr) {
    asm volatile("ldmatrix.sync.aligned.m8n8.x4.shared.b16 {%0,%1,%2,%3}, [%4];\n"
                 : "=r"(r0), "=r"(r1), "=r"(r2), "=r"(r3)
                 : "r"(addr));
}
__device__ __forceinline__ void mma16816(float* c, const uint32_t* a,
                                         uint32_t b0, uint32_t b1) {
    asm volatile(
        "mma.sync.aligned.m16n8k16.row.col.f32.bf16.bf16.f32 "
        "{%0,%1,%2,%3}, {%4,%5,%6,%7}, {%8,%9}, {%0,%1,%2,%3};\n"
        : "+f"(c[0]), "+f"(c[1]), "+f"(c[2]), "+f"(c[3])
        : "r"(a[0]), "r"(a[1]), "r"(a[2]), "r"(a[3]), "r"(b0), "r"(b1));
}

// ---------------------------------------------------------------------------
// Kernel 1: per-pair normalize (rows p and p+B), fused positive-pair dot.
// Also zeros rowsums and the output scalar. grid = BHALF, 128 threads.
// ---------------------------------------------------------------------------
__global__ void __launch_bounds__(128) normalize_kernel(const float* __restrict__ zi,
                                                        const float* __restrict__ zj,
                                                        float* __restrict__ d_out) {
    const int p = blockIdx.x;
    const int t = threadIdx.x;
    float4 vi = ((const float4*)(zi + (size_t)p * DIM))[t];
    float4 vj = ((const float4*)(zj + (size_t)p * DIM))[t];
    float ssi = vi.x * vi.x + vi.y * vi.y + vi.z * vi.z + vi.w * vi.w;
    float ssj = vj.x * vj.x + vj.y * vj.y + vj.z * vj.z + vj.w * vj.w;
    float sij = vi.x * vj.x + vi.y * vj.y + vi.z * vj.z + vi.w * vj.w;
    #pragma unroll
    for (int o = 16; o; o >>= 1) {
        ssi += __shfl_xor_sync(0xffffffffu, ssi, o);
        ssj += __shfl_xor_sync(0xffffffffu, ssj, o);
        sij += __shfl_xor_sync(0xffffffffu, sij, o);
    }
    __shared__ float s0[4], s1[4], s2[4];
    if ((t & 31) == 0) { s0[t >> 5] = ssi; s1[t >> 5] = ssj; s2[t >> 5] = sij; }
    __syncthreads();
    float rni = rsqrtf(s0[0] + s0[1] + s0[2] + s0[3]);
    float rnj = rsqrtf(s1[0] + s1[1] + s1[2] + s1[3]);

    __nv_bfloat162* di = (__nv_bfloat162*)(g_zn + (size_t)p * DIM) + t * 2;
    di[0] = __float22bfloat162_rn(make_float2(vi.x * rni, vi.y * rni));
    di[1] = __float22bfloat162_rn(make_float2(vi.z * rni, vi.w * rni));
    __nv_bfloat162* dj = (__nv_bfloat162*)(g_zn + (size_t)(p + BHALF) * DIM) + t * 2;
    dj[0] = __float22bfloat162_rn(make_float2(vj.x * rnj, vj.y * rnj));
    dj[1] = __float22bfloat162_rn(make_float2(vj.z * rnj, vj.w * rnj));

    if (t == 0) {
        g_posdot[p] = (s2[0] + s2[1] + s2[2] + s2[3]) * rni * rnj;
        g_rowsum[p] = 0.0f;
        g_rowsum[p + BHALF] = 0.0f;
        if (p == 0) d_out[0] = 0.0f;
    }
}

// ---------------------------------------------------------------------------
// Kernel 2: symmetric bf16 mma.sync GEMM + fused exp + row/col sums.
// grid = 2080 upper-triangular 128x128 tiles, 128 threads (4 warps, 64x64 each,
// warp grid 2M x 2N). cp.async 2-stage pipelined K loop, double-buffered
// ldmatrix fragments. Keep elements with global col > row; each kept exp adds
// to rowsum[row] and rowsum[col].
// ---------------------------------------------------------------------------
__global__ void __launch_bounds__(128, 2) gemm_rowsum_kernel() {
    extern __shared__ __nv_bfloat16 sm[];

    // decode upper-tri tile index
    int id = blockIdx.x, rt = 0, rem = NTILE;
    while (id >= rem) { id -= rem; rem--; rt++; }
    const int ct = rt + id;
    const int rowA0 = rt * TILE, rowB0 = ct * TILE;
    const bool isDiag = (rt == ct);

    const int tid  = threadIdx.x;
    const int warp = tid >> 5, lane = tid & 31;
    const int wm = warp & 1;       // warp row (0..1): 64 rows
    const int wn = warp >> 1;      // warp col (0..1): 64 cols

    float acc[4][8][4];
    #pragma unroll
    for (int i = 0; i < 4; i++)
        #pragma unroll
        for (int j = 0; j < 8; j++)
            #pragma unroll
            for (int k = 0; k < 4; k++) acc[i][j][k] = 0.0f;

    // ---- async chunk loader: A (and B unless diag) 128x64 bf16 into stage st
    auto issue_load = [&](int k0, int st) {
        uint32_t sA = smem_u32(sm) + st * STAGE_BYTES;
        uint32_t sB = sA + MAT_BYTES;
        const __nv_bfloat16* gA = g_zn + (size_t)rowA0 * DIM + k0;
        const __nv_bfloat16* gB = g_zn + (size_t)rowB0 * DIM + k0;
        #pragma unroll
        for (int i = 0; i < 8; i++) {
            int lin = tid + i * 128;          // 0..1023
            int r  = lin >> 3;
            int c8 = (lin & 7) << 3;
            uint32_t soff = r * (LDST * 2) + c8 * 2;   // bytes; 144*r is 16B-aligned
            cpasync16(sA + soff, gA + (size_t)r * DIM + c8);
            if (!isDiag) cpasync16(sB + soff, gB + (size_t)r * DIM + c8);
        }
        asm volatile("cp.async.commit_group;\n" ::: "memory");
    };

    // fragment loaders for one k16 step
    auto load_frags = [&](const __nv_bfloat16* As, const __nv_bfloat16* Bs, int kk,
                          uint32_t a[4][4], uint32_t b[4][4]) {
        #pragma unroll
        for (int mf = 0; mf < 4; mf++) {
            int row = wm * 64 + mf * 16 + (lane & 15);
            int kc  = kk * 16 + (lane >> 4) * 8;
            ldmat_x4(a[mf][0], a[mf][1], a[mf][2], a[mf][3],
                     smem_u32(As + row * LDST + kc));
        }
        #pragma unroll
        for (int nn = 0; nn < 4; nn++) {
            int grp = lane >> 3;
            int nr  = wn * 64 + nn * 16 + (lane & 7) + ((grp >> 1) << 3);
            int kc  = kk * 16 + ((grp & 1) << 3);
            ldmat_x4(b[nn][0], b[nn][1], b[nn][2], b[nn][3],
                     smem_u32(Bs + nr * LDST + kc));
        }
    };
    auto do_mmas = [&](uint32_t a[4][4], uint32_t b[4][4]) {
        #pragma unroll
        for (int mf = 0; mf < 4; mf++)
            #pragma unroll
            for (int nn = 0; nn < 4; nn++) {
                mma16816(acc[mf][nn * 2 + 0], a[mf], b[nn][0], b[nn][1]);
                mma16816(acc[mf][nn * 2 + 1], a[mf], b[nn][2], b[nn][3]);
            }
    };

    issue_load(0, 0);
    #pragma unroll 1
    for (int k = 0; k < NKCH; k++) {
        if (k + 1 < NKCH) {
            issue_load((k + 1) * KCH, (k + 1) & 1);
            asm volatile("cp.async.wait_group 1;\n" ::: "memory");
        } else {
            asm volatile("cp.async.wait_group 0;\n" ::: "memory");
        }
        __syncthreads();

        const __nv_bfloat16* As = sm + (k & 1) * (STAGE_BYTES / 2);
        const __nv_bfloat16* Bs = isDiag ? As : (As + TILE * LDST);
        uint32_t fa[2][4][4], fb[2][4][4];
        load_frags(As, Bs, 0, fa[0], fb[0]);
        #pragma unroll
        for (int kk = 0; kk < 4; kk++) {
            if (kk < 3) load_frags(As, Bs, kk + 1, fa[(kk + 1) & 1], fb[(kk + 1) & 1]);
            do_mmas(fa[kk & 1], fb[kk & 1]);
        }
        __syncthreads();   // all warps done reading before next load overwrites
    }

    // ---- epilogue: exp(2*dot); keep col>row (full off-diag tiles, strict upper
    //      on diag tiles); accumulate row sums and column sums.
    float rs[4][2];
    #pragma unroll
    for (int mf = 0; mf < 4; mf++) { rs[mf][0] = 0.f; rs[mf][1] = 0.f; }
    float cs[8][2];
    #pragma unroll
    for (int nf = 0; nf < 8; nf++) { cs[nf][0] = 0.f; cs[nf][1] = 0.f; }

    #pragma unroll
    for (int mf = 0; mf < 4; mf++) {
        int ra = rowA0 + wm * 64 + mf * 16 + (lane >> 2);
        int rb = ra + 8;
        #pragma unroll
        for (int nf = 0; nf < 8; nf++) {
            int c0 = rowB0 + wn * 64 + nf * 8 + ((lane & 3) << 1);
            float e0 = __expf(2.0f * acc[mf][nf][0]);
            float e1 = __expf(2.0f * acc[mf][nf][1]);
            float e2 = __expf(2.0f * acc[mf][nf][2]);
            float e3 = __expf(2.0f * acc[mf][nf][3]);
            if (isDiag) {
                if (c0     <= ra) e0 = 0.f;
                if (c0 + 1 <= ra) e1 = 0.f;
                if (c0     <= rb) e2 = 0.f;
                if (c0 + 1 <= rb) e3 = 0.f;
            }
            rs[mf][0] += e0 + e1;
            rs[mf][1] += e2 + e3;
            cs[nf][0] += e0 + e2;
            cs[nf][1] += e1 + e3;
        }
    }

    // row sums: reduce across lane&3 (4 threads share a row)
    #pragma unroll
    for (int mf = 0; mf < 4; mf++) {
        #pragma unroll
        for (int o = 1; o < 4; o <<= 1) {
            rs[mf][0] += __shfl_xor_sync(0xffffffffu, rs[mf][0], o);
            rs[mf][1] += __shfl_xor_sync(0xffffffffu, rs[mf][1], o);
        }
    }
    if ((lane & 3) == 0) {
        int r0 = rowA0 + wm * 64 + (lane >> 2);
        #pragma unroll
        for (int mf = 0; mf < 4; mf++) {
            atomicAdd(&g_rowsum[r0 + mf * 16],     rs[mf][0]);
            atomicAdd(&g_rowsum[r0 + mf * 16 + 8], rs[mf][1]);
        }
    }

    // col sums: reduce across lane>>2 (8 threads share a column group)
    #pragma unroll
    for (int nf = 0; nf < 8; nf++) {
        #pragma unroll
        for (int o = 4; o < 32; o <<= 1) {
            cs[nf][0] += __shfl_xor_sync(0xffffffffu, cs[nf][0], o);
            cs[nf][1] += __shfl_xor_sync(0xffffffffu, cs[nf][1], o);
        }
    }
    if (lane < 4) {
        #pragma unroll
        for (int nf = 0; nf < 8; nf++) {
            int c0 = rowB0 + wn * 64 + nf * 8 + lane * 2;
            atomicAdd(&g_rowsum[c0],     cs[nf][0]);
            atomicAdd(&g_rowsum[c0 + 1], cs[nf][1]);
        }
    }
}

// ---------------------------------------------------------------------------
// Kernel 3: final loss.
// loss = -(1/2B) * sum_p [4*posdot(p) - log(rs_p) - log(rs_{p+B})]
// ---------------------------------------------------------------------------
__global__ void __launch_bounds__(128) loss_kernel(float* __restrict__ d_out) {
    const int p = blockIdx.x * 128 + threadIdx.x;
    float c = 4.0f * g_posdot[p] - logf(g_rowsum[p]) - logf(g_rowsum[p + BHALF]);
    #pragma unroll
    for (int o = 16; o; o >>= 1) c += __shfl_xor_sync(0xffffffffu, c, o);
    __shared__ float ws[4];
    int t = threadIdx.x;
    if ((t & 31) == 0) ws[t >> 5] = c;
    __syncthreads();
    if (t == 0)
        atomicAdd(d_out, (ws[0] + ws[1] + ws[2] + ws[3]) * (-1.0f / (float)NROWS));
}

// ---------------------------------------------------------------------------
extern "C" void kernel_launch(void* const* d_in, const int* in_sizes, int n_in,
                              void* d_out, int out_size) {
    const float* zi = (const float*)d_in[0];
    const float* zj = (const float*)d_in[1];
    float* out = (float*)d_out;

    static bool attr_set = false;
    if (!attr_set) {
        cudaFuncSetAttribute(gemm_rowsum_kernel,
                             cudaFuncAttributeMaxDynamicSharedMemorySize, SMEM_BYTES);
        attr_set = true;
    }

    normalize_kernel<<<BHALF, 128>>>(zi, zj, out);
    gemm_rowsum_kernel<<<NBLK, 128, SMEM_BYTES>>>();
    loss_kernel<<<32, 128>>>(out);
}